// round 14
// baseline (speedup 1.0000x reference)
#include <cuda_runtime.h>
#include <cstdint>

typedef unsigned char u8;
typedef unsigned int u32;

#define BATCH 4096

// ---------------- static device scratch ----------------
__device__ __align__(16)  short g_S1[25 * 256 * 8];     // conv1 s16 residuals [k][a][8], scale 4096
__device__ __align__(16)  short g_S2[150 * 128 * 16];   // conv2 s16 residuals, unit-swizzled, scale 4096
__device__ __align__(16)  short g_T3[256 * 128 * 120];  // fc1 s16 residuals [k][a][120], scale 8192
__device__ __align__(128) float g_M4[120 * 128 * 84];   // fc2
__device__ __align__(128) float g_M5[84 * 128 * 10];    // fc3

__device__ float g_h1[BATCH * 6 * 144];
__device__ float g_h2[BATCH * 256];
__device__ float g_h3[BATCH * 120];
__device__ float g_h4[BATCH * 84];

__device__ u8 g_qw1[150], g_qw2[2400], g_qw3[30720], g_qw4[10080], g_qw5[840];
__device__ __align__(16) u32 g_pw1[72];      // conv1 packed signed weights [o=6][12 words]
__device__ __align__(16) u32 g_pw2[1152];    // conv2 packed signed weights [o=16][c=6][12 words]
__device__ __align__(16) u32 g_pw3t[64 * 128]; // fc1 packed signed weights, transposed [word][o pad128]
__device__ float g_sw[5];
__device__ u32 g_amax[5];   // monotone max-abs (float bits); zero-init at load, replay-stable

// ---------------- helpers ----------------
__device__ __forceinline__ float act_scale(int i) {
    float m = __uint_as_float(g_amax[i]);
    return __fdiv_rn(m, 127.0f) + 1e-8f;
}

__device__ __forceinline__ float blockReduceMax(float v, float* sred) {
    #pragma unroll
    for (int off = 16; off; off >>= 1)
        v = fmaxf(v, __shfl_xor_sync(0xFFFFFFFFu, v, off));
    int w = threadIdx.x >> 5;
    int nw = (blockDim.x + 31) >> 5;
    if ((threadIdx.x & 31) == 0) sred[w] = v;
    __syncthreads();
    if (threadIdx.x < 32) {
        v = (threadIdx.x < nw) ? sred[threadIdx.x] : 0.0f;
        #pragma unroll
        for (int off = 16; off; off >>= 1)
            v = fmaxf(v, __shfl_xor_sync(0xFFFFFFFFu, v, off));
    }
    return v;
}

__device__ __forceinline__ u8 quant1(float v, float s) {
    float q = rintf(__fdiv_rn(v, s));
    q = fminf(fmaxf(q, -128.0f), 127.0f);
    return (u8)((int)q + 128);
}

// ---------------- setup: weight quant/pack (blocks 0-4) + maxabs(x) (blocks 5+) ----------------
__global__ void k_setup(const float* w0, const float* w1, const float* w2,
                        const float* w3, const float* w4, const float* x, int nx) {
    __shared__ float sred[32];
    __shared__ float ss;
    int l = blockIdx.x;
    if (l >= 5) {
        float m = 0.0f;
        int start = (l - 5) * blockDim.x + threadIdx.x;
        int stride = (gridDim.x - 5) * blockDim.x;
        for (int i = start; i < nx; i += stride) m = fmaxf(m, fabsf(x[i]));
        m = blockReduceMax(m, sred);
        if (threadIdx.x == 0) atomicMax(&g_amax[0], __float_as_uint(m));
        return;
    }
    const float* w; int n; u8* dst;
    if      (l == 0) { w = w0; n = 150;   dst = g_qw1; }
    else if (l == 1) { w = w1; n = 2400;  dst = g_qw2; }
    else if (l == 2) { w = w2; n = 30720; dst = g_qw3; }
    else if (l == 3) { w = w3; n = 10080; dst = g_qw4; }
    else             { w = w4; n = 840;   dst = g_qw5; }
    float m = 0.0f;
    for (int i = threadIdx.x; i < n; i += blockDim.x) m = fmaxf(m, fabsf(w[i]));
    m = blockReduceMax(m, sred);
    if (threadIdx.x == 0) {
        float s = __fdiv_rn(m, 127.0f) + 1e-8f;
        g_sw[l] = s; ss = s;
    }
    __syncthreads();
    float s = ss;
    for (int i = threadIdx.x; i < n; i += blockDim.x) dst[i] = quant1(w[i], s);
    __syncthreads();
    if (l == 0) {
        for (int t = threadIdx.x; t < 72; t += blockDim.x) {
            int o = t / 12, w12 = t % 12;
            u32 word = 0;
            if (w12 < 10) {
                int i = w12 >> 1;
                #pragma unroll
                for (int bt = 0; bt < 4; bt++) {
                    int j = (w12 & 1) * 4 + bt;
                    if (j < 5)
                        word |= (u32)(u8)(g_qw1[o * 25 + i * 5 + j] ^ 0x80) << (8 * bt);
                }
            }
            g_pw1[t] = word;
        }
    }
    if (l == 1) {
        for (int t = threadIdx.x; t < 1152; t += blockDim.x) {
            int o = t / 72, rem = t % 72, c = rem / 12, w12 = rem % 12;
            u32 word = 0;
            if (w12 < 10) {
                int i = w12 >> 1;
                #pragma unroll
                for (int bt = 0; bt < 4; bt++) {
                    int j = (w12 & 1) * 4 + bt;
                    if (j < 5)
                        word |= (u32)(u8)(g_qw2[o * 150 + c * 25 + i * 5 + j] ^ 0x80) << (8 * bt);
                }
            }
            g_pw2[t] = word;
        }
    }
    if (l == 2) {   // fc1 transposed pack: word w, output o -> bytes qw3[o*256 + 4w .. +3]
        for (int t = threadIdx.x; t < 64 * 128; t += blockDim.x) {
            int w12 = t >> 7, o = t & 127;
            u32 word = 0;
            if (o < 120) {
                #pragma unroll
                for (int bt = 0; bt < 4; bt++)
                    word |= (u32)(u8)(g_qw3[o * 256 + w12 * 4 + bt] ^ 0x80) << (8 * bt);
            }
            g_pw3t[t] = word;
        }
    }
}

// ---------------- fused residual-table build (conv1 + conv2, s16 scale 4096) ----------------
#define S1_TOT (25 * 256 * 8)
#define S2_TOT (150 * 128 * 16)
__global__ void k_buildS12(const float* lut) {
    int i = blockIdx.x * blockDim.x + threadIdx.x;
    if (i < S1_TOT) {
        int k = i >> 11, a = (i >> 3) & 255, o = i & 7;
        float v = 0.0f;
        if (o < 6) {
            int qwi = g_qw1[o * 25 + k];
            v = lut[a * 256 + qwi] - (float)((a - 128) * (qwi - 128));
        }
        float sv = rintf(v * 4096.0f);
        sv = fminf(fmaxf(sv, -32767.0f), 32767.0f);
        g_S1[(k * 256 + a) * 8 + o] = (short)sv;
    } else if (i < S1_TOT + S2_TOT) {
        int j = i - S1_TOT;
        int k = j >> 11, a = (j >> 4) & 127, o = j & 15;
        int qwi = g_qw2[o * 150 + k];
        float v = lut[(a + 128) * 256 + qwi] - (float)(a * (qwi - 128));
        float sv = rintf(v * 4096.0f);
        sv = fminf(fmaxf(sv, -32767.0f), 32767.0f);
        int unit = 2 * a + ((o >> 3) ^ ((a >> 2) & 1));
        g_S2[k * 2048 + unit * 8 + (o & 7)] = (short)sv;
    }
}

// ---------------- fused table build: fc1 s16 residual (scale 8192) + fc2/fc3 fp32 ----------------
#define T3_TOT (256 * 128 * 120)
#define M4_TOT (120 * 128 * 84)
#define M5_TOT (84 * 128 * 10)
__global__ void k_buildT345(const float* lut) {
    int total = T3_TOT + M4_TOT + M5_TOT;
    for (int i = blockIdx.x * blockDim.x + threadIdx.x; i < total;
         i += gridDim.x * blockDim.x) {
        if (i < T3_TOT) {
            int k = i / (128 * 120);
            int r = i - k * (128 * 120);
            int a = r / 120;
            int o = r - a * 120;
            int qwi = g_qw3[o * 256 + k];
            float v = lut[(a + 128) * 256 + qwi] - (float)(a * (qwi - 128));
            float sv = rintf(v * 8192.0f);
            sv = fminf(fmaxf(sv, -32767.0f), 32767.0f);
            g_T3[i] = (short)sv;
        } else if (i < T3_TOT + M4_TOT) {
            int rem = i - T3_TOT;
            int k = rem / (128 * 84);
            int r = rem - k * (128 * 84);
            int a = r / 84;
            int o = r - a * 84;
            g_M4[rem] = lut[(a + 128) * 256 + (int)g_qw4[o * 120 + k]];
        } else {
            int rem = i - T3_TOT - M4_TOT;
            int k = rem / (128 * 10);
            int r = rem - k * (128 * 10);
            int a = r / 10;
            int o = r - a * 10;
            g_M5[rem] = lut[(a + 128) * 256 + (int)g_qw5[o * 84 + k]];
        }
    }
}

// ---------------- conv1: dp4a exact int + smem s16 residual (dp2a exact), 2 blocks/SM ----------------
#define C1_SMEM (102400 + 3136 + 128)

__global__ void __launch_bounds__(576, 2) k_conv1(const float* x, const float* b1) {
    extern __shared__ char smemc[];
    uint4* tbl = (uint4*)smemc;                         // 6400 uint4 = 102400 B
    u8* qimg = (u8*)(smemc + 102400);                   // 3136 bytes
    float* sred = (float*)(smemc + 102400 + 3136);

    int tid = threadIdx.x;
    {
        const uint4* src = (const uint4*)g_S1;
        for (int i = tid; i < 6400; i += 576) tbl[i] = src[i];
    }
    float s0 = act_scale(0);
    float sc = s0 * g_sw[0];
    float bb[6];
    #pragma unroll
    for (int o = 0; o < 6; o++) bb[o] = __ldg(b1 + o);

    int img = tid / 144, pos = tid - img * 144;
    int py = pos / 12, px = pos - py * 12;
    const u32* qword = (const u32*)qimg;
    float mymax = 0.0f;

    for (int g = blockIdx.x; g < BATCH / 4; g += gridDim.x) {
        __syncthreads();
        const float* xs = x + (size_t)g * 3136;
        for (int i = tid; i < 3136; i += 576) qimg[i] = quant1(xs[i], s0) ^ 0x80;
        __syncthreads();

        float best[6] = {0, 0, 0, 0, 0, 0};
        #pragma unroll
        for (int dy = 0; dy < 2; dy++) {
            #pragma unroll
            for (int dx = 0; dx < 2; dx++) {
                int boff0 = img * 784 + (py * 2 + dy) * 28 + (px * 2 + dx);
                u32 qa[10];
                #pragma unroll
                for (int i2 = 0; i2 < 5; i2++) {
                    int boff = boff0 + i2 * 28;
                    u32 w0 = qword[boff >> 2], w1 = qword[(boff >> 2) + 1];
                    int sh = (boff & 3) * 8;
                    qa[2 * i2]     = __funnelshift_r(w0, w1, sh);
                    qa[2 * i2 + 1] = (w1 >> sh) & 0xFF;
                }
                int P[6];
                #pragma unroll
                for (int o = 0; o < 6; o++) {
                    const uint4* pwo = (const uint4*)g_pw1 + o * 3;
                    uint4 A = __ldg(pwo), B = __ldg(pwo + 1), C = __ldg(pwo + 2);
                    int a = 0;
                    a = __dp4a((int)qa[0], (int)A.x, a);
                    a = __dp4a((int)qa[1], (int)A.y, a);
                    a = __dp4a((int)qa[2], (int)A.z, a);
                    a = __dp4a((int)qa[3], (int)A.w, a);
                    a = __dp4a((int)qa[4], (int)B.x, a);
                    a = __dp4a((int)qa[5], (int)B.y, a);
                    a = __dp4a((int)qa[6], (int)B.z, a);
                    a = __dp4a((int)qa[7], (int)B.w, a);
                    a = __dp4a((int)qa[8], (int)C.x, a);
                    a = __dp4a((int)qa[9], (int)C.y, a);
                    P[o] = a;
                }
                int r0 = 0, r1 = 0, r2 = 0, r3 = 0, r4 = 0, r5 = 0;
                #pragma unroll
                for (int k = 0; k < 25; k++) {
                    int i2 = k / 5, j = k % 5;
                    int a = (int)((qa[2 * i2 + (j >> 2)] >> (8 * (j & 3))) & 0xFF) ^ 0x80;
                    uint4 u = tbl[k * 256 + a];
                    r0 = __dp2a_lo((int)u.x, 0x00000001, r0);
                    r1 = __dp2a_lo((int)u.x, 0x00000100, r1);
                    r2 = __dp2a_lo((int)u.y, 0x00000001, r2);
                    r3 = __dp2a_lo((int)u.y, 0x00000100, r3);
                    r4 = __dp2a_lo((int)u.z, 0x00000001, r4);
                    r5 = __dp2a_lo((int)u.z, 0x00000100, r5);
                }
                int R[6] = {r0, r1, r2, r3, r4, r5};
                #pragma unroll
                for (int o = 0; o < 6; o++) {
                    float t = (float)P[o] + (float)R[o] * (1.0f / 4096.0f);
                    float v = fmaxf(sc * t + bb[o], 0.0f);
                    best[o] = fmaxf(best[o], v);
                }
            }
        }
        int b = g * 4 + img;
        #pragma unroll
        for (int o = 0; o < 6; o++) {
            g_h1[(size_t)(b * 6 + o) * 144 + pos] = best[o];
            mymax = fmaxf(mymax, best[o]);
        }
    }
    float bm = blockReduceMax(mymax, sred);
    if (tid == 0) atomicMax(&g_amax[1], __float_as_uint(bm));
}

// ---------------- conv2: dp4a exact int + s16 residual (dp2a exact), slice streaming ----------------
__global__ void __launch_bounds__(512) k_conv2(const float* b2) {
    __shared__ __align__(16) u8 sImg[8 * 864 + 16];
    __shared__ uint4 ring[4][256];     // 4 x 4KB s16 residual slices
    __shared__ float sred[32];

    int blk = blockIdx.x, tid = threadIdx.x;
    float s1 = act_scale(1);

    const float* hsrc = g_h1 + (size_t)blk * 6912;
    for (int i = tid; i < 6912; i += 512) sImg[i] = quant1(hsrc[i], s1) ^ 0x80; // ai in [0,127]
    if (tid < 16) sImg[6912 + tid] = 0;

    const uint4* Q2 = (const uint4*)g_S2;     // slice k = [k*256, +256)
    ring[tid >> 8][tid & 255] = Q2[tid];              // slices 0,1
    ring[2 + (tid >> 8)][tid & 255] = Q2[512 + tid];  // slices 2,3
    __syncthreads();

    int img = tid >> 6, pos = tid & 63;
    int y = pos >> 3, xx = pos & 7;
    int base0 = img * 864 + y * 12 + xx;
    const u32* qword = (const u32*)sImg;

    // phase 1: exact integer product part via dp4a
    int P[16];
    #pragma unroll
    for (int o = 0; o < 16; o++) P[o] = 0;
    #pragma unroll
    for (int c = 0; c < 6; c++) {
        u32 qa[10];
        #pragma unroll
        for (int i2 = 0; i2 < 5; i2++) {
            int boff = base0 + c * 144 + i2 * 12;
            u32 w0 = qword[boff >> 2], w1 = qword[(boff >> 2) + 1];
            int sh = (boff & 3) * 8;
            qa[i2 * 2]     = __funnelshift_r(w0, w1, sh);
            qa[i2 * 2 + 1] = (w1 >> sh) & 0xFF;
        }
        #pragma unroll
        for (int o = 0; o < 16; o++) {
            const uint4* pwo = (const uint4*)g_pw2 + (o * 6 + c) * 3;
            uint4 A = __ldg(pwo), B = __ldg(pwo + 1), C = __ldg(pwo + 2);
            int a = P[o];
            a = __dp4a((int)qa[0], (int)A.x, a);
            a = __dp4a((int)qa[1], (int)A.y, a);
            a = __dp4a((int)qa[2], (int)A.z, a);
            a = __dp4a((int)qa[3], (int)A.w, a);
            a = __dp4a((int)qa[4], (int)B.x, a);
            a = __dp4a((int)qa[5], (int)B.y, a);
            a = __dp4a((int)qa[6], (int)B.z, a);
            a = __dp4a((int)qa[7], (int)B.w, a);
            a = __dp4a((int)qa[8], (int)C.x, a);
            a = __dp4a((int)qa[9], (int)C.y, a);
            P[o] = a;
        }
    }

    // phase 2: s16 residual, exact s32 accumulation via dp2a, k-major slice streaming
    int racc[16];
    #pragma unroll
    for (int o = 0; o < 16; o++) racc[o] = 0;
    const u8* ibase = sImg + base0;
    int off = 0, jc = 0, ic = 0;
    for (int p = 0; p < 75; p++) {
        uint4 pre;
        bool more = (p < 73);
        if (more) pre = Q2[(2 * p + 4) * 256 + tid];   // slices 2p+4 (tid<256), 2p+5 (tid>=256)
        #pragma unroll
        for (int kk = 0; kk < 2; kk++) {
            int k = 2 * p + kk;
            int ai = ibase[off];
            const uint4* sb = ring[k & 3];
            int t = (ai >> 2) & 1;
            uint4 u0 = sb[2 * ai + t];        // o0-7
            uint4 u1 = sb[2 * ai + (t ^ 1)];  // o8-15
            racc[0]  = __dp2a_lo((int)u0.x, 0x00000001, racc[0]);
            racc[1]  = __dp2a_lo((int)u0.x, 0x00000100, racc[1]);
            racc[2]  = __dp2a_lo((int)u0.y, 0x00000001, racc[2]);
            racc[3]  = __dp2a_lo((int)u0.y, 0x00000100, racc[3]);
            racc[4]  = __dp2a_lo((int)u0.z, 0x00000001, racc[4]);
            racc[5]  = __dp2a_lo((int)u0.z, 0x00000100, racc[5]);
            racc[6]  = __dp2a_lo((int)u0.w, 0x00000001, racc[6]);
            racc[7]  = __dp2a_lo((int)u0.w, 0x00000100, racc[7]);
            racc[8]  = __dp2a_lo((int)u1.x, 0x00000001, racc[8]);
            racc[9]  = __dp2a_lo((int)u1.x, 0x00000100, racc[9]);
            racc[10] = __dp2a_lo((int)u1.y, 0x00000001, racc[10]);
            racc[11] = __dp2a_lo((int)u1.y, 0x00000100, racc[11]);
            racc[12] = __dp2a_lo((int)u1.z, 0x00000001, racc[12]);
            racc[13] = __dp2a_lo((int)u1.z, 0x00000100, racc[13]);
            racc[14] = __dp2a_lo((int)u1.w, 0x00000001, racc[14]);
            racc[15] = __dp2a_lo((int)u1.w, 0x00000100, racc[15]);
            off++; jc++;
            if (jc == 5) { jc = 0; off += 7; ic++; if (ic == 5) { ic = 0; off += 84; } }
        }
        __syncthreads();
        if (more) ring[(2 * p + (tid >> 8)) & 3][tid & 255] = pre;
    }

    float s = s1 * g_sw[1];
    float v[16];
    #pragma unroll
    for (int o = 0; o < 16; o++)
        v[o] = fmaxf(s * ((float)P[o] + (float)racc[o] * (1.0f / 4096.0f)) + __ldg(b2 + o), 0.0f);

    #pragma unroll
    for (int o = 0; o < 16; o++) {
        v[o] = fmaxf(v[o], __shfl_xor_sync(0xFFFFFFFFu, v[o], 1));
        v[o] = fmaxf(v[o], __shfl_xor_sync(0xFFFFFFFFu, v[o], 8));
    }
    int lane = tid & 31;
    float mymax = 0.0f;
    if (!(lane & 1) && !(lane & 8)) {
        int ppy = y >> 1, ppx = xx >> 1;
        int b = blk * 8 + img;
        #pragma unroll
        for (int o = 0; o < 16; o++) {
            g_h2[(size_t)b * 256 + o * 16 + ppy * 4 + ppx] = v[o];
            mymax = fmaxf(mymax, v[o]);
        }
    }
    float bm = blockReduceMax(mymax, sred);
    if (tid == 0) atomicMax(&g_amax[2], __float_as_uint(bm));
}

// ---------------- fc1: dp4a exact int + s16 residual rows (coalesced LDG) ----------------
__global__ void __launch_bounds__(128) k_fc1(const float* fcb) {
    __shared__ __align__(4) u8 qb[256];
    __shared__ float sred[32];
    int b = blockIdx.x, tid = threadIdx.x;
    float s2 = act_scale(2);
    // A = q-128 in [0,127] (post-relu): byte serves as both dp4a operand and table index
    qb[tid]       = quant1(g_h2[(size_t)b * 256 + tid], s2) ^ 0x80;
    qb[tid + 128] = quant1(g_h2[(size_t)b * 256 + tid + 128], s2) ^ 0x80;
    __syncthreads();

    float val = 0.0f;
    if (tid < 120) {
        const u32* qw = (const u32*)qb;
        int P = 0;
        #pragma unroll 8
        for (int w = 0; w < 64; w++)
            P = __dp4a((int)qw[w], (int)__ldg(&g_pw3t[w * 128 + tid]), P);
        int racc = 0;
        #pragma unroll 8
        for (int k = 0; k < 256; k++) {
            int ai = qb[k];
            racc += (int)__ldg(&g_T3[(size_t)(k * 128 + ai) * 120 + tid]);
        }
        float s = s2 * g_sw[2];
        val = fmaxf(s * ((float)P + (float)racc * (1.0f / 8192.0f)) + __ldg(fcb + tid), 0.0f);
        g_h3[(size_t)b * 120 + tid] = val;
    }
    float bm = blockReduceMax(val, sred);
    if (tid == 0) atomicMax(&g_amax[3], __float_as_uint(bm));
}

// ---------------- fc2 ----------------
__global__ void __launch_bounds__(96) k_fc2(const float* fcb) {
    __shared__ u8 q[120];
    __shared__ float sred[32];
    int b = blockIdx.x, tid = threadIdx.x;
    float s3 = act_scale(3);
    for (int i = tid; i < 120; i += 96) q[i] = quant1(g_h3[(size_t)b * 120 + i], s3);
    __syncthreads();
    float acc = 0.0f;
    if (tid < 84) {
        #pragma unroll 8
        for (int k = 0; k < 120; k++) {
            int ai = (int)q[k] - 128;
            acc += __ldg(&g_M4[(size_t)(k * 128 + ai) * 84 + tid]);
        }
    }
    float s = s3 * g_sw[3];
    float val = 0.0f;
    if (tid < 84) {
        val = fmaxf(s * acc + __ldg(fcb + tid), 0.0f);
        g_h4[(size_t)b * 84 + tid] = val;
    }
    float bm = blockReduceMax(val, sred);
    if (tid == 0) atomicMax(&g_amax[4], __float_as_uint(bm));
}

// ---------------- fc3 ----------------
__global__ void __launch_bounds__(96) k_fc3(const float* fcb, float* out) {
    __shared__ u8 q[84];
    int b = blockIdx.x, tid = threadIdx.x;
    float s4 = act_scale(4);
    if (tid < 84) q[tid] = quant1(g_h4[(size_t)b * 84 + tid], s4);
    __syncthreads();
    if (tid < 10) {
        float acc = 0.0f;
        #pragma unroll 4
        for (int k = 0; k < 84; k++) {
            int ai = (int)q[k] - 128;
            acc += __ldg(&g_M5[(k * 128 + ai) * 10 + tid]);
        }
        out[b * 10 + tid] = s4 * g_sw[4] * acc + __ldg(fcb + tid);
    }
}

// ---------------- launch ----------------
extern "C" void kernel_launch(void* const* d_in, const int* in_sizes, int n_in,
                              void* d_out, int out_size) {
    const float* x   = (const float*)d_in[0];
    const float* lut = (const float*)d_in[1];
    const float* w1  = (const float*)d_in[2];
    const float* b1  = (const float*)d_in[3];
    const float* w2  = (const float*)d_in[4];
    const float* b2  = (const float*)d_in[5];
    const float* w3  = (const float*)d_in[6];
    const float* b3  = (const float*)d_in[7];
    const float* w4  = (const float*)d_in[8];
    const float* b4  = (const float*)d_in[9];
    const float* w5  = (const float*)d_in[10];
    const float* b5  = (const float*)d_in[11];
    float* out = (float*)d_out;

    cudaFuncSetAttribute(k_conv1, cudaFuncAttributeMaxDynamicSharedMemorySize, C1_SMEM);

    int nx = BATCH * 784;
    k_setup<<<5 + 2048, 256>>>(w1, w2, w3, w4, w5, x, nx);              // 1
    k_buildS12<<<(S1_TOT + S2_TOT + 255) / 256, 256>>>(lut);            // 2
    k_conv1<<<296, 576, C1_SMEM>>>(x, b1);                              // 3
    k_conv2<<<BATCH / 8, 512>>>(b2);                                    // 4  <- profiled
    k_buildT345<<<10000, 256>>>(lut);                                   // 5
    k_fc1<<<BATCH, 128>>>(b3);                                          // 6
    k_fc2<<<BATCH, 96>>>(b4);                                           // 7
    k_fc3<<<BATCH, 96>>>(b5, out);                                      // 8
}

// round 15
// speedup vs baseline: 1.0914x; 1.0914x over previous
#include <cuda_runtime.h>
#include <cstdint>

typedef unsigned char u8;
typedef unsigned int u32;

#define BATCH 4096

// ---------------- static device scratch ----------------
__device__ __align__(16)  short g_S1[25 * 256 * 8];     // conv1 s16 residuals [k][a][8], scale 4096
__device__ __align__(16)  short g_S2[150 * 128 * 16];   // conv2 s16 residuals, unit-swizzled, scale 4096
__device__ __align__(128) float g_M3[256 * 128 * 120];  // fc1
__device__ __align__(128) float g_M4[120 * 128 * 84];   // fc2
__device__ __align__(128) float g_M5[84 * 128 * 10];    // fc3

__device__ float g_h1[BATCH * 6 * 144];
__device__ float g_h2[BATCH * 256];
__device__ float g_h3[BATCH * 120];
__device__ float g_h4[BATCH * 84];

__device__ u8 g_qw1[150], g_qw2[2400], g_qw3[30720], g_qw4[10080], g_qw5[840];
__device__ __align__(16) u32 g_pw1[72];     // conv1 packed signed weights [o=6][12 words]
__device__ __align__(16) u32 g_pw2[1152];   // conv2 packed signed weights [o=16][c=6][12 words]
__device__ float g_sw[5];
__device__ u32 g_amax[5];   // monotone max-abs (float bits); zero-init at load, replay-stable

// ---------------- helpers ----------------
__device__ __forceinline__ float act_scale(int i) {
    float m = __uint_as_float(g_amax[i]);
    return __fdiv_rn(m, 127.0f) + 1e-8f;
}

__device__ __forceinline__ float blockReduceMax(float v, float* sred) {
    #pragma unroll
    for (int off = 16; off; off >>= 1)
        v = fmaxf(v, __shfl_xor_sync(0xFFFFFFFFu, v, off));
    int w = threadIdx.x >> 5;
    int nw = (blockDim.x + 31) >> 5;
    if ((threadIdx.x & 31) == 0) sred[w] = v;
    __syncthreads();
    if (threadIdx.x < 32) {
        v = (threadIdx.x < nw) ? sred[threadIdx.x] : 0.0f;
        #pragma unroll
        for (int off = 16; off; off >>= 1)
            v = fmaxf(v, __shfl_xor_sync(0xFFFFFFFFu, v, off));
    }
    return v;
}

__device__ __forceinline__ u8 quant1(float v, float s) {
    float q = rintf(__fdiv_rn(v, s));
    q = fminf(fmaxf(q, -128.0f), 127.0f);
    return (u8)((int)q + 128);
}

// ---------------- setup: weight quant/pack (blocks 0-4) + maxabs(x) (blocks 5+) ----------------
__global__ void k_setup(const float* w0, const float* w1, const float* w2,
                        const float* w3, const float* w4, const float* x, int nx) {
    __shared__ float sred[32];
    __shared__ float ss;
    int l = blockIdx.x;
    if (l >= 5) {
        float m = 0.0f;
        int start = (l - 5) * blockDim.x + threadIdx.x;
        int stride = (gridDim.x - 5) * blockDim.x;
        for (int i = start; i < nx; i += stride) m = fmaxf(m, fabsf(x[i]));
        m = blockReduceMax(m, sred);
        if (threadIdx.x == 0) atomicMax(&g_amax[0], __float_as_uint(m));
        return;
    }
    const float* w; int n; u8* dst;
    if      (l == 0) { w = w0; n = 150;   dst = g_qw1; }
    else if (l == 1) { w = w1; n = 2400;  dst = g_qw2; }
    else if (l == 2) { w = w2; n = 30720; dst = g_qw3; }
    else if (l == 3) { w = w3; n = 10080; dst = g_qw4; }
    else             { w = w4; n = 840;   dst = g_qw5; }
    float m = 0.0f;
    for (int i = threadIdx.x; i < n; i += blockDim.x) m = fmaxf(m, fabsf(w[i]));
    m = blockReduceMax(m, sred);
    if (threadIdx.x == 0) {
        float s = __fdiv_rn(m, 127.0f) + 1e-8f;
        g_sw[l] = s; ss = s;
    }
    __syncthreads();
    float s = ss;
    for (int i = threadIdx.x; i < n; i += blockDim.x) dst[i] = quant1(w[i], s);
    __syncthreads();
    if (l == 0) {
        for (int t = threadIdx.x; t < 72; t += blockDim.x) {
            int o = t / 12, w12 = t % 12;
            u32 word = 0;
            if (w12 < 10) {
                int i = w12 >> 1;
                #pragma unroll
                for (int bt = 0; bt < 4; bt++) {
                    int j = (w12 & 1) * 4 + bt;
                    if (j < 5)
                        word |= (u32)(u8)(g_qw1[o * 25 + i * 5 + j] ^ 0x80) << (8 * bt);
                }
            }
            g_pw1[t] = word;
        }
    }
    if (l == 1) {
        for (int t = threadIdx.x; t < 1152; t += blockDim.x) {
            int o = t / 72, rem = t % 72, c = rem / 12, w12 = rem % 12;
            u32 word = 0;
            if (w12 < 10) {
                int i = w12 >> 1;
                #pragma unroll
                for (int bt = 0; bt < 4; bt++) {
                    int j = (w12 & 1) * 4 + bt;
                    if (j < 5)
                        word |= (u32)(u8)(g_qw2[o * 150 + c * 25 + i * 5 + j] ^ 0x80) << (8 * bt);
                }
            }
            g_pw2[t] = word;
        }
    }
}

// ---------------- fused residual-table build (conv1 + conv2, s16 scale 4096) ----------------
#define S1_TOT (25 * 256 * 8)
#define S2_TOT (150 * 128 * 16)
__global__ void k_buildS12(const float* lut) {
    int i = blockIdx.x * blockDim.x + threadIdx.x;
    if (i < S1_TOT) {
        int k = i >> 11, a = (i >> 3) & 255, o = i & 7;
        float v = 0.0f;
        if (o < 6) {
            int qwi = g_qw1[o * 25 + k];
            v = lut[a * 256 + qwi] - (float)((a - 128) * (qwi - 128));
        }
        float sv = rintf(v * 4096.0f);
        sv = fminf(fmaxf(sv, -32767.0f), 32767.0f);
        g_S1[(k * 256 + a) * 8 + o] = (short)sv;
    } else if (i < S1_TOT + S2_TOT) {
        int j = i - S1_TOT;
        int k = j >> 11, a = (j >> 4) & 127, o = j & 15;
        int qwi = g_qw2[o * 150 + k];
        float v = lut[(a + 128) * 256 + qwi] - (float)(a * (qwi - 128));
        float sv = rintf(v * 4096.0f);
        sv = fminf(fmaxf(sv, -32767.0f), 32767.0f);
        int unit = 2 * a + ((o >> 3) ^ ((a >> 2) & 1));
        g_S2[k * 2048 + unit * 8 + (o & 7)] = (short)sv;
    }
}

// ---------------- fused fc table build (fp32, round-13 proven) ----------------
#define M3_TOT (256 * 128 * 120)
#define M4_TOT (120 * 128 * 84)
#define M5_TOT (84 * 128 * 10)
__global__ void k_buildM345(const float* lut) {
    int total = M3_TOT + M4_TOT + M5_TOT;
    for (int i = blockIdx.x * blockDim.x + threadIdx.x; i < total;
         i += gridDim.x * blockDim.x) {
        int rem = i; const u8* qw; float* dst; int K, O;
        if (rem < M3_TOT)                { K = 256; O = 120; qw = g_qw3; dst = g_M3; }
        else if (rem < M3_TOT + M4_TOT)  { rem -= M3_TOT; K = 120; O = 84; qw = g_qw4; dst = g_M4; }
        else                             { rem -= M3_TOT + M4_TOT; K = 84; O = 10; qw = g_qw5; dst = g_M5; }
        int k = rem / (128 * O);
        int r = rem - k * (128 * O);
        int a = r / O;
        int o = r - a * O;
        dst[rem] = lut[(a + 128) * 256 + (int)qw[o * K + k]];
    }
}

// ---------------- conv1: 2 img x 144 pos x 2 dy-windows; dy-pool via shfl ----------------
#define C1_SMEM (102400 + 1568 + 128)

__global__ void __launch_bounds__(576, 2) k_conv1(const float* x, const float* b1) {
    extern __shared__ char smemc[];
    uint4* tbl = (uint4*)smemc;                         // 6400 uint4 = 102400 B
    u8* qimg = (u8*)(smemc + 102400);                   // 1568 bytes (2 images)
    float* sred = (float*)(smemc + 102400 + 1568);

    int tid = threadIdx.x;
    {
        const uint4* src = (const uint4*)g_S1;
        for (int i = tid; i < 6400; i += 576) tbl[i] = src[i];
    }
    float s0 = act_scale(0);
    float sc = s0 * g_sw[0];
    float bb[6];
    #pragma unroll
    for (int o = 0; o < 6; o++) bb[o] = __ldg(b1 + o);

    int img = tid / 288;
    int r   = tid - img * 288;
    int pos = r >> 1, dy = r & 1;       // dy pairs are adjacent lanes
    int py = pos / 12, px = pos - py * 12;
    const u32* qword = (const u32*)qimg;
    float mymax = 0.0f;

    for (int g = blockIdx.x; g < BATCH / 2; g += gridDim.x) {
        __syncthreads();   // table ready (iter 0) / prior qimg reads done
        const float* xs = x + (size_t)g * 1568;
        for (int i = tid; i < 1568; i += 576) qimg[i] = quant1(xs[i], s0) ^ 0x80;
        __syncthreads();

        float best[6] = {0, 0, 0, 0, 0, 0};
        #pragma unroll
        for (int dx = 0; dx < 2; dx++) {
            int boff0 = img * 784 + (py * 2 + dy) * 28 + (px * 2 + dx);
            u32 qa[10];
            #pragma unroll
            for (int i2 = 0; i2 < 5; i2++) {
                int boff = boff0 + i2 * 28;
                u32 w0 = qword[boff >> 2], w1 = qword[(boff >> 2) + 1];
                int sh = (boff & 3) * 8;
                qa[2 * i2]     = __funnelshift_r(w0, w1, sh);
                qa[2 * i2 + 1] = (w1 >> sh) & 0xFF;
            }
            int P[6];
            #pragma unroll
            for (int o = 0; o < 6; o++) {
                const uint4* pwo = (const uint4*)g_pw1 + o * 3;
                uint4 A = __ldg(pwo), B = __ldg(pwo + 1), C = __ldg(pwo + 2);
                int a = 0;
                a = __dp4a((int)qa[0], (int)A.x, a);
                a = __dp4a((int)qa[1], (int)A.y, a);
                a = __dp4a((int)qa[2], (int)A.z, a);
                a = __dp4a((int)qa[3], (int)A.w, a);
                a = __dp4a((int)qa[4], (int)B.x, a);
                a = __dp4a((int)qa[5], (int)B.y, a);
                a = __dp4a((int)qa[6], (int)B.z, a);
                a = __dp4a((int)qa[7], (int)B.w, a);
                a = __dp4a((int)qa[8], (int)C.x, a);
                a = __dp4a((int)qa[9], (int)C.y, a);
                P[o] = a;
            }
            int r0 = 0, r1 = 0, r2 = 0, r3 = 0, r4 = 0, r5 = 0;
            #pragma unroll
            for (int k = 0; k < 25; k++) {
                int i2 = k / 5, j = k % 5;
                int a = (int)((qa[2 * i2 + (j >> 2)] >> (8 * (j & 3))) & 0xFF) ^ 0x80;
                uint4 u = tbl[k * 256 + a];
                r0 = __dp2a_lo((int)u.x, 0x00000001, r0);
                r1 = __dp2a_lo((int)u.x, 0x00000100, r1);
                r2 = __dp2a_lo((int)u.y, 0x00000001, r2);
                r3 = __dp2a_lo((int)u.y, 0x00000100, r3);
                r4 = __dp2a_lo((int)u.z, 0x00000001, r4);
                r5 = __dp2a_lo((int)u.z, 0x00000100, r5);
            }
            int R[6] = {r0, r1, r2, r3, r4, r5};
            #pragma unroll
            for (int o = 0; o < 6; o++) {
                float t = (float)P[o] + (float)R[o] * (1.0f / 4096.0f);
                float v = fmaxf(sc * t + bb[o], 0.0f);
                best[o] = fmaxf(best[o], v);
            }
        }
        // pool over dy: pairs are adjacent lanes
        #pragma unroll
        for (int o = 0; o < 6; o++)
            best[o] = fmaxf(best[o], __shfl_xor_sync(0xFFFFFFFFu, best[o], 1));
        if (dy == 0) {
            int b = g * 2 + img;
            #pragma unroll
            for (int o = 0; o < 6; o++) {
                g_h1[(size_t)(b * 6 + o) * 144 + pos] = best[o];
                mymax = fmaxf(mymax, best[o]);
            }
        }
    }
    float bm = blockReduceMax(mymax, sred);
    if (tid == 0) atomicMax(&g_amax[1], __float_as_uint(bm));
}

// ---------------- conv2: dp4a exact int + s16 residual (dp2a exact), slice streaming ----------------
__global__ void __launch_bounds__(512) k_conv2(const float* b2) {
    __shared__ __align__(16) u8 sImg[8 * 864 + 16];
    __shared__ uint4 ring[4][256];     // 4 x 4KB s16 residual slices
    __shared__ float sred[32];

    int blk = blockIdx.x, tid = threadIdx.x;
    float s1 = act_scale(1);

    const float* hsrc = g_h1 + (size_t)blk * 6912;
    for (int i = tid; i < 6912; i += 512) sImg[i] = quant1(hsrc[i], s1) ^ 0x80; // ai in [0,127]
    if (tid < 16) sImg[6912 + tid] = 0;

    const uint4* Q2 = (const uint4*)g_S2;     // slice k = [k*256, +256)
    ring[tid >> 8][tid & 255] = Q2[tid];              // slices 0,1
    ring[2 + (tid >> 8)][tid & 255] = Q2[512 + tid];  // slices 2,3
    __syncthreads();

    int img = tid >> 6, pos = tid & 63;
    int y = pos >> 3, xx = pos & 7;
    int base0 = img * 864 + y * 12 + xx;
    const u32* qword = (const u32*)sImg;

    // phase 1: exact integer product part via dp4a
    int P[16];
    #pragma unroll
    for (int o = 0; o < 16; o++) P[o] = 0;
    #pragma unroll
    for (int c = 0; c < 6; c++) {
        u32 qa[10];
        #pragma unroll
        for (int i2 = 0; i2 < 5; i2++) {
            int boff = base0 + c * 144 + i2 * 12;
            u32 w0 = qword[boff >> 2], w1 = qword[(boff >> 2) + 1];
            int sh = (boff & 3) * 8;
            qa[i2 * 2]     = __funnelshift_r(w0, w1, sh);
            qa[i2 * 2 + 1] = (w1 >> sh) & 0xFF;
        }
        #pragma unroll
        for (int o = 0; o < 16; o++) {
            const uint4* pwo = (const uint4*)g_pw2 + (o * 6 + c) * 3;
            uint4 A = __ldg(pwo), B = __ldg(pwo + 1), C = __ldg(pwo + 2);
            int a = P[o];
            a = __dp4a((int)qa[0], (int)A.x, a);
            a = __dp4a((int)qa[1], (int)A.y, a);
            a = __dp4a((int)qa[2], (int)A.z, a);
            a = __dp4a((int)qa[3], (int)A.w, a);
            a = __dp4a((int)qa[4], (int)B.x, a);
            a = __dp4a((int)qa[5], (int)B.y, a);
            a = __dp4a((int)qa[6], (int)B.z, a);
            a = __dp4a((int)qa[7], (int)B.w, a);
            a = __dp4a((int)qa[8], (int)C.x, a);
            a = __dp4a((int)qa[9], (int)C.y, a);
            P[o] = a;
        }
    }

    // phase 2: s16 residual, exact s32 accumulation via dp2a, k-major slice streaming
    int racc[16];
    #pragma unroll
    for (int o = 0; o < 16; o++) racc[o] = 0;
    const u8* ibase = sImg + base0;
    int off = 0, jc = 0, ic = 0;
    for (int p = 0; p < 75; p++) {
        uint4 pre;
        bool more = (p < 73);
        if (more) pre = Q2[(2 * p + 4) * 256 + tid];   // slices 2p+4 (tid<256), 2p+5 (tid>=256)
        #pragma unroll
        for (int kk = 0; kk < 2; kk++) {
            int k = 2 * p + kk;
            int ai = ibase[off];
            const uint4* sb = ring[k & 3];
            int t = (ai >> 2) & 1;
            uint4 u0 = sb[2 * ai + t];        // o0-7
            uint4 u1 = sb[2 * ai + (t ^ 1)];  // o8-15
            racc[0]  = __dp2a_lo((int)u0.x, 0x00000001, racc[0]);
            racc[1]  = __dp2a_lo((int)u0.x, 0x00000100, racc[1]);
            racc[2]  = __dp2a_lo((int)u0.y, 0x00000001, racc[2]);
            racc[3]  = __dp2a_lo((int)u0.y, 0x00000100, racc[3]);
            racc[4]  = __dp2a_lo((int)u0.z, 0x00000001, racc[4]);
            racc[5]  = __dp2a_lo((int)u0.z, 0x00000100, racc[5]);
            racc[6]  = __dp2a_lo((int)u0.w, 0x00000001, racc[6]);
            racc[7]  = __dp2a_lo((int)u0.w, 0x00000100, racc[7]);
            racc[8]  = __dp2a_lo((int)u1.x, 0x00000001, racc[8]);
            racc[9]  = __dp2a_lo((int)u1.x, 0x00000100, racc[9]);
            racc[10] = __dp2a_lo((int)u1.y, 0x00000001, racc[10]);
            racc[11] = __dp2a_lo((int)u1.y, 0x00000100, racc[11]);
            racc[12] = __dp2a_lo((int)u1.z, 0x00000001, racc[12]);
            racc[13] = __dp2a_lo((int)u1.z, 0x00000100, racc[13]);
            racc[14] = __dp2a_lo((int)u1.w, 0x00000001, racc[14]);
            racc[15] = __dp2a_lo((int)u1.w, 0x00000100, racc[15]);
            off++; jc++;
            if (jc == 5) { jc = 0; off += 7; ic++; if (ic == 5) { ic = 0; off += 84; } }
        }
        __syncthreads();
        if (more) ring[(2 * p + (tid >> 8)) & 3][tid & 255] = pre;
    }

    float s = s1 * g_sw[1];
    float v[16];
    #pragma unroll
    for (int o = 0; o < 16; o++)
        v[o] = fmaxf(s * ((float)P[o] + (float)racc[o] * (1.0f / 4096.0f)) + __ldg(b2 + o), 0.0f);

    #pragma unroll
    for (int o = 0; o < 16; o++) {
        v[o] = fmaxf(v[o], __shfl_xor_sync(0xFFFFFFFFu, v[o], 1));
        v[o] = fmaxf(v[o], __shfl_xor_sync(0xFFFFFFFFu, v[o], 8));
    }
    int lane = tid & 31;
    float mymax = 0.0f;
    if (!(lane & 1) && !(lane & 8)) {
        int ppy = y >> 1, ppx = xx >> 1;
        int b = blk * 8 + img;
        #pragma unroll
        for (int o = 0; o < 16; o++) {
            g_h2[(size_t)b * 256 + o * 16 + ppy * 4 + ppx] = v[o];
            mymax = fmaxf(mymax, v[o]);
        }
    }
    float bm = blockReduceMax(mymax, sred);
    if (tid == 0) atomicMax(&g_amax[2], __float_as_uint(bm));
}

// ---------------- fc1 (round-13 proven) ----------------
__global__ void __launch_bounds__(128) k_fc1(const float* fcb) {
    __shared__ u8 q[256];
    __shared__ float sred[32];
    int b = blockIdx.x, tid = threadIdx.x;
    float s2 = act_scale(2);
    for (int i = tid; i < 256; i += 128) q[i] = quant1(g_h2[(size_t)b * 256 + i], s2);
    __syncthreads();
    float acc = 0.0f;
    if (tid < 120) {
        #pragma unroll 8
        for (int k = 0; k < 256; k++) {
            int ai = (int)q[k] - 128;
            acc += __ldg(&g_M3[(size_t)(k * 128 + ai) * 120 + tid]);
        }
    }
    float s = s2 * g_sw[2];
    float val = 0.0f;
    if (tid < 120) {
        val = fmaxf(s * acc + __ldg(fcb + tid), 0.0f);
        g_h3[(size_t)b * 120 + tid] = val;
    }
    float bm = blockReduceMax(val, sred);
    if (tid == 0) atomicMax(&g_amax[3], __float_as_uint(bm));
}

// ---------------- fc2 ----------------
__global__ void __launch_bounds__(96) k_fc2(const float* fcb) {
    __shared__ u8 q[120];
    __shared__ float sred[32];
    int b = blockIdx.x, tid = threadIdx.x;
    float s3 = act_scale(3);
    for (int i = tid; i < 120; i += 96) q[i] = quant1(g_h3[(size_t)b * 120 + i], s3);
    __syncthreads();
    float acc = 0.0f;
    if (tid < 84) {
        #pragma unroll 8
        for (int k = 0; k < 120; k++) {
            int ai = (int)q[k] - 128;
            acc += __ldg(&g_M4[(size_t)(k * 128 + ai) * 84 + tid]);
        }
    }
    float s = s3 * g_sw[3];
    float val = 0.0f;
    if (tid < 84) {
        val = fmaxf(s * acc + __ldg(fcb + tid), 0.0f);
        g_h4[(size_t)b * 84 + tid] = val;
    }
    float bm = blockReduceMax(val, sred);
    if (tid == 0) atomicMax(&g_amax[4], __float_as_uint(bm));
}

// ---------------- fc3 ----------------
__global__ void __launch_bounds__(96) k_fc3(const float* fcb, float* out) {
    __shared__ u8 q[84];
    int b = blockIdx.x, tid = threadIdx.x;
    float s4 = act_scale(4);
    if (tid < 84) q[tid] = quant1(g_h4[(size_t)b * 84 + tid], s4);
    __syncthreads();
    if (tid < 10) {
        float acc = 0.0f;
        #pragma unroll 4
        for (int k = 0; k < 84; k++) {
            int ai = (int)q[k] - 128;
            acc += __ldg(&g_M5[(k * 128 + ai) * 10 + tid]);
        }
        out[b * 10 + tid] = s4 * g_sw[4] * acc + __ldg(fcb + tid);
    }
}

// ---------------- launch ----------------
extern "C" void kernel_launch(void* const* d_in, const int* in_sizes, int n_in,
                              void* d_out, int out_size) {
    const float* x   = (const float*)d_in[0];
    const float* lut = (const float*)d_in[1];
    const float* w1  = (const float*)d_in[2];
    const float* b1  = (const float*)d_in[3];
    const float* w2  = (const float*)d_in[4];
    const float* b2  = (const float*)d_in[5];
    const float* w3  = (const float*)d_in[6];
    const float* b3  = (const float*)d_in[7];
    const float* w4  = (const float*)d_in[8];
    const float* b4  = (const float*)d_in[9];
    const float* w5  = (const float*)d_in[10];
    const float* b5  = (const float*)d_in[11];
    float* out = (float*)d_out;

    cudaFuncSetAttribute(k_conv1, cudaFuncAttributeMaxDynamicSharedMemorySize, C1_SMEM);

    int nx = BATCH * 784;
    k_setup<<<5 + 2048, 256>>>(w1, w2, w3, w4, w5, x, nx);              // 1
    k_buildS12<<<(S1_TOT + S2_TOT + 255) / 256, 256>>>(lut);            // 2
    k_conv1<<<296, 576, C1_SMEM>>>(x, b1);                              // 3
    k_conv2<<<BATCH / 8, 512>>>(b2);                                    // 4  <- profiled
    k_buildM345<<<20832, 256>>>(lut);                                   // 5
    k_fc1<<<BATCH, 128>>>(b3);                                          // 6
    k_fc2<<<BATCH, 96>>>(b4);                                           // 7
    k_fc3<<<BATCH, 96>>>(b5, out);                                      // 8
}

// round 16
// speedup vs baseline: 1.1400x; 1.0445x over previous
#include <cuda_runtime.h>
#include <cstdint>

typedef unsigned char u8;
typedef unsigned int u32;

#define BATCH 4096

// ---------------- static device scratch ----------------
__device__ __align__(16)  short g_S1[25 * 256 * 8];     // conv1 s16 residuals [k][a][8], scale 4096
__device__ __align__(16)  short g_S2[150 * 128 * 16];   // conv2 s16 residuals, unit-swizzled, scale 4096
__device__ __align__(128) float g_M3[256 * 128 * 120];  // fc1
__device__ __align__(128) float g_M4[120 * 128 * 84];   // fc2
__device__ __align__(128) float g_M5[84 * 128 * 10];    // fc3

__device__ float g_h1[BATCH * 6 * 144];
__device__ float g_h2[BATCH * 256];
__device__ float g_h3[BATCH * 120];
__device__ float g_h4[BATCH * 84];

__device__ u8 g_qw1[150], g_qw2[2400], g_qw3[30720], g_qw4[10080], g_qw5[840];
__device__ __align__(16) u32 g_pw1[72];     // conv1 packed signed weights [o=6][12 words]
__device__ __align__(16) u32 g_pw2[1152];   // conv2 packed signed weights [o=16][c=6][12 words]
__device__ float g_sw[5];
__device__ u32 g_amax[5];   // monotone max-abs (float bits); zero-init at load, replay-stable

// ---------------- helpers ----------------
__device__ __forceinline__ float act_scale(int i) {
    float m = __uint_as_float(g_amax[i]);
    return __fdiv_rn(m, 127.0f) + 1e-8f;
}

__device__ __forceinline__ float blockReduceMax(float v, float* sred) {
    #pragma unroll
    for (int off = 16; off; off >>= 1)
        v = fmaxf(v, __shfl_xor_sync(0xFFFFFFFFu, v, off));
    int w = threadIdx.x >> 5;
    int nw = (blockDim.x + 31) >> 5;
    if ((threadIdx.x & 31) == 0) sred[w] = v;
    __syncthreads();
    if (threadIdx.x < 32) {
        v = (threadIdx.x < nw) ? sred[threadIdx.x] : 0.0f;
        #pragma unroll
        for (int off = 16; off; off >>= 1)
            v = fmaxf(v, __shfl_xor_sync(0xFFFFFFFFu, v, off));
    }
    return v;
}

__device__ __forceinline__ u8 quant1(float v, float s) {
    float q = rintf(__fdiv_rn(v, s));
    q = fminf(fmaxf(q, -128.0f), 127.0f);
    return (u8)((int)q + 128);
}

// ---------------- setup: weight quant/pack (blocks 0-4) + maxabs(x) (blocks 5+) ----------------
__global__ void k_setup(const float* w0, const float* w1, const float* w2,
                        const float* w3, const float* w4, const float* x, int nx) {
    __shared__ float sred[32];
    __shared__ float ss;
    int l = blockIdx.x;
    if (l >= 5) {
        float m = 0.0f;
        int start = (l - 5) * blockDim.x + threadIdx.x;
        int stride = (gridDim.x - 5) * blockDim.x;
        for (int i = start; i < nx; i += stride) m = fmaxf(m, fabsf(x[i]));
        m = blockReduceMax(m, sred);
        if (threadIdx.x == 0) atomicMax(&g_amax[0], __float_as_uint(m));
        return;
    }
    const float* w; int n; u8* dst;
    if      (l == 0) { w = w0; n = 150;   dst = g_qw1; }
    else if (l == 1) { w = w1; n = 2400;  dst = g_qw2; }
    else if (l == 2) { w = w2; n = 30720; dst = g_qw3; }
    else if (l == 3) { w = w3; n = 10080; dst = g_qw4; }
    else             { w = w4; n = 840;   dst = g_qw5; }
    float m = 0.0f;
    for (int i = threadIdx.x; i < n; i += blockDim.x) m = fmaxf(m, fabsf(w[i]));
    m = blockReduceMax(m, sred);
    if (threadIdx.x == 0) {
        float s = __fdiv_rn(m, 127.0f) + 1e-8f;
        g_sw[l] = s; ss = s;
    }
    __syncthreads();
    float s = ss;
    for (int i = threadIdx.x; i < n; i += blockDim.x) dst[i] = quant1(w[i], s);
    __syncthreads();
    if (l == 0) {
        for (int t = threadIdx.x; t < 72; t += blockDim.x) {
            int o = t / 12, w12 = t % 12;
            u32 word = 0;
            if (w12 < 10) {
                int i = w12 >> 1;
                #pragma unroll
                for (int bt = 0; bt < 4; bt++) {
                    int j = (w12 & 1) * 4 + bt;
                    if (j < 5)
                        word |= (u32)(u8)(g_qw1[o * 25 + i * 5 + j] ^ 0x80) << (8 * bt);
                }
            }
            g_pw1[t] = word;
        }
    }
    if (l == 1) {
        for (int t = threadIdx.x; t < 1152; t += blockDim.x) {
            int o = t / 72, rem = t % 72, c = rem / 12, w12 = rem % 12;
            u32 word = 0;
            if (w12 < 10) {
                int i = w12 >> 1;
                #pragma unroll
                for (int bt = 0; bt < 4; bt++) {
                    int j = (w12 & 1) * 4 + bt;
                    if (j < 5)
                        word |= (u32)(u8)(g_qw2[o * 150 + c * 25 + i * 5 + j] ^ 0x80) << (8 * bt);
                }
            }
            g_pw2[t] = word;
        }
    }
}

// ---------------- fused residual-table build (conv1 + conv2, s16 scale 4096) ----------------
#define S1_TOT (25 * 256 * 8)
#define S2_TOT (150 * 128 * 16)
__global__ void k_buildS12(const float* lut) {
    int i = blockIdx.x * blockDim.x + threadIdx.x;
    if (i < S1_TOT) {
        int k = i >> 11, a = (i >> 3) & 255, o = i & 7;
        float v = 0.0f;
        if (o < 6) {
            int qwi = g_qw1[o * 25 + k];
            v = lut[a * 256 + qwi] - (float)((a - 128) * (qwi - 128));
        }
        float sv = rintf(v * 4096.0f);
        sv = fminf(fmaxf(sv, -32767.0f), 32767.0f);
        g_S1[(k * 256 + a) * 8 + o] = (short)sv;
    } else if (i < S1_TOT + S2_TOT) {
        int j = i - S1_TOT;
        int k = j >> 11, a = (j >> 4) & 127, o = j & 15;
        int qwi = g_qw2[o * 150 + k];
        float v = lut[(a + 128) * 256 + qwi] - (float)(a * (qwi - 128));
        float sv = rintf(v * 4096.0f);
        sv = fminf(fmaxf(sv, -32767.0f), 32767.0f);
        int unit = 2 * a + ((o >> 3) ^ ((a >> 2) & 1));
        g_S2[k * 2048 + unit * 8 + (o & 7)] = (short)sv;
    }
}

// ---------------- fused fc table build (fp32) ----------------
#define M3_TOT (256 * 128 * 120)
#define M4_TOT (120 * 128 * 84)
#define M5_TOT (84 * 128 * 10)
__global__ void k_buildM345(const float* lut) {
    int total = M3_TOT + M4_TOT + M5_TOT;
    for (int i = blockIdx.x * blockDim.x + threadIdx.x; i < total;
         i += gridDim.x * blockDim.x) {
        int rem = i; const u8* qw; float* dst; int K, O;
        if (rem < M3_TOT)                { K = 256; O = 120; qw = g_qw3; dst = g_M3; }
        else if (rem < M3_TOT + M4_TOT)  { rem -= M3_TOT; K = 120; O = 84; qw = g_qw4; dst = g_M4; }
        else                             { rem -= M3_TOT + M4_TOT; K = 84; O = 10; qw = g_qw5; dst = g_M5; }
        int k = rem / (128 * O);
        int r = rem - k * (128 * O);
        int a = r / O;
        int o = r - a * O;
        dst[rem] = lut[(a + 128) * 256 + (int)qw[o * K + k]];
    }
}

// ---------------- conv1: 1 img x 144 pos x 4 windows; pool via 2 shuffles ----------------
#define C1_SMEM (102400 + 784 + 128)

__global__ void __launch_bounds__(576, 2) k_conv1(const float* x, const float* b1) {
    extern __shared__ char smemc[];
    uint4* tbl = (uint4*)smemc;                         // 6400 uint4 = 102400 B
    u8* qimg = (u8*)(smemc + 102400);                   // 784 bytes (1 image)
    float* sred = (float*)(smemc + 102400 + 784);

    int tid = threadIdx.x;
    {
        const uint4* src = (const uint4*)g_S1;
        for (int i = tid; i < 6400; i += 576) tbl[i] = src[i];
    }
    float s0 = act_scale(0);
    float sc = s0 * g_sw[0];
    float bb[6];
    #pragma unroll
    for (int o = 0; o < 6; o++) bb[o] = __ldg(b1 + o);

    int pos = tid >> 2, w = tid & 3;        // w: bit0 = dx, bit1 = dy (lane-adjacent)
    int dy = w >> 1, dx = w & 1;
    int py = pos / 12, px = pos - py * 12;
    const u32* qword = (const u32*)qimg;
    float mymax = 0.0f;

    for (int g = blockIdx.x; g < BATCH; g += gridDim.x) {
        __syncthreads();   // table ready (iter 0) / prior qimg reads done
        const float* xs = x + (size_t)g * 784;
        for (int i = tid; i < 784; i += 576) qimg[i] = quant1(xs[i], s0) ^ 0x80;
        __syncthreads();

        int boff0 = (py * 2 + dy) * 28 + (px * 2 + dx);
        u32 qa[10];
        #pragma unroll
        for (int i2 = 0; i2 < 5; i2++) {
            int boff = boff0 + i2 * 28;
            u32 w0 = qword[boff >> 2], w1 = qword[(boff >> 2) + 1];
            int sh = (boff & 3) * 8;
            qa[2 * i2]     = __funnelshift_r(w0, w1, sh);
            qa[2 * i2 + 1] = (w1 >> sh) & 0xFF;
        }
        int P[6];
        #pragma unroll
        for (int o = 0; o < 6; o++) {
            const uint4* pwo = (const uint4*)g_pw1 + o * 3;
            uint4 A = __ldg(pwo), B = __ldg(pwo + 1), C = __ldg(pwo + 2);
            int a = 0;
            a = __dp4a((int)qa[0], (int)A.x, a);
            a = __dp4a((int)qa[1], (int)A.y, a);
            a = __dp4a((int)qa[2], (int)A.z, a);
            a = __dp4a((int)qa[3], (int)A.w, a);
            a = __dp4a((int)qa[4], (int)B.x, a);
            a = __dp4a((int)qa[5], (int)B.y, a);
            a = __dp4a((int)qa[6], (int)B.z, a);
            a = __dp4a((int)qa[7], (int)B.w, a);
            a = __dp4a((int)qa[8], (int)C.x, a);
            a = __dp4a((int)qa[9], (int)C.y, a);
            P[o] = a;
        }
        int r0 = 0, r1 = 0, r2 = 0, r3 = 0, r4 = 0, r5 = 0;
        #pragma unroll
        for (int k = 0; k < 25; k++) {
            int i2 = k / 5, j = k % 5;
            int a = (int)((qa[2 * i2 + (j >> 2)] >> (8 * (j & 3))) & 0xFF) ^ 0x80;
            uint4 u = tbl[k * 256 + a];
            r0 = __dp2a_lo((int)u.x, 0x00000001, r0);
            r1 = __dp2a_lo((int)u.x, 0x00000100, r1);
            r2 = __dp2a_lo((int)u.y, 0x00000001, r2);
            r3 = __dp2a_lo((int)u.y, 0x00000100, r3);
            r4 = __dp2a_lo((int)u.z, 0x00000001, r4);
            r5 = __dp2a_lo((int)u.z, 0x00000100, r5);
        }
        int R[6] = {r0, r1, r2, r3, r4, r5};
        float best[6];
        #pragma unroll
        for (int o = 0; o < 6; o++) {
            float t = (float)P[o] + (float)R[o] * (1.0f / 4096.0f);
            best[o] = fmaxf(sc * t + bb[o], 0.0f);
        }
        // 2x2 pool: dx pairs (xor 1), dy pairs (xor 2)
        #pragma unroll
        for (int o = 0; o < 6; o++) {
            best[o] = fmaxf(best[o], __shfl_xor_sync(0xFFFFFFFFu, best[o], 1));
            best[o] = fmaxf(best[o], __shfl_xor_sync(0xFFFFFFFFu, best[o], 2));
        }
        if (w == 0) {
            #pragma unroll
            for (int o = 0; o < 6; o++) {
                g_h1[(size_t)(g * 6 + o) * 144 + pos] = best[o];
                mymax = fmaxf(mymax, best[o]);
            }
        }
    }
    float bm = blockReduceMax(mymax, sred);
    if (tid == 0) atomicMax(&g_amax[1], __float_as_uint(bm));
}

// ---------------- conv2: dp4a exact int + s16 residual; 4-k windows, 1 barrier each ----------------
__global__ void __launch_bounds__(512, 2) k_conv2(const float* b2) {
    __shared__ __align__(16) u8 sImg[8 * 864 + 16];
    __shared__ uint4 ring[2][4][256];   // 2 groups x 4 slices x 4KB = 32KB
    __shared__ float sred[32];

    int blk = blockIdx.x, tid = threadIdx.x;
    float s1 = act_scale(1);

    const float* hsrc = g_h1 + (size_t)blk * 6912;
    for (int i = tid; i < 6912; i += 512) sImg[i] = quant1(hsrc[i], s1) ^ 0x80; // ai in [0,127]
    if (tid < 16) sImg[6912 + tid] = 0;

    const uint4* Q2 = (const uint4*)g_S2;     // slice k = [k*256, +256); total 38400 uint4
    int t8 = tid >> 8;                        // 0/1
    uint4 pre0 = Q2[tid];                     // slices 0,1
    uint4 pre1 = Q2[512 + tid];               // slices 2,3
    __syncthreads();                          // sImg ready

    int img = tid >> 6, pos = tid & 63;
    int y = pos >> 3, xx = pos & 7;
    int base0 = img * 864 + y * 12 + xx;
    const u32* qword = (const u32*)sImg;

    // phase 1: exact integer product part via dp4a
    int P[16];
    #pragma unroll
    for (int o = 0; o < 16; o++) P[o] = 0;
    #pragma unroll
    for (int c = 0; c < 6; c++) {
        u32 qa[10];
        #pragma unroll
        for (int i2 = 0; i2 < 5; i2++) {
            int boff = base0 + c * 144 + i2 * 12;
            u32 w0 = qword[boff >> 2], w1 = qword[(boff >> 2) + 1];
            int sh = (boff & 3) * 8;
            qa[i2 * 2]     = __funnelshift_r(w0, w1, sh);
            qa[i2 * 2 + 1] = (w1 >> sh) & 0xFF;
        }
        #pragma unroll
        for (int o = 0; o < 16; o++) {
            const uint4* pwo = (const uint4*)g_pw2 + (o * 6 + c) * 3;
            uint4 A = __ldg(pwo), B = __ldg(pwo + 1), C = __ldg(pwo + 2);
            int a = P[o];
            a = __dp4a((int)qa[0], (int)A.x, a);
            a = __dp4a((int)qa[1], (int)A.y, a);
            a = __dp4a((int)qa[2], (int)A.z, a);
            a = __dp4a((int)qa[3], (int)A.w, a);
            a = __dp4a((int)qa[4], (int)B.x, a);
            a = __dp4a((int)qa[5], (int)B.y, a);
            a = __dp4a((int)qa[6], (int)B.z, a);
            a = __dp4a((int)qa[7], (int)B.w, a);
            a = __dp4a((int)qa[8], (int)C.x, a);
            a = __dp4a((int)qa[9], (int)C.y, a);
            P[o] = a;
        }
    }

    // phase 2: s16 residual; write group -> prefetch -> barrier -> 4-k window
    int racc[16];
    #pragma unroll
    for (int o = 0; o < 16; o++) racc[o] = 0;
    const u8* ibase = sImg + base0;
    int off = 0, jc = 0, ic = 0;
    for (int p = 0; p < 37; p++) {             // k = 4p .. 4p+3 (0..147)
        int grp = p & 1;
        ring[grp][t8][tid & 255]     = pre0;   // slices 4p, 4p+1
        ring[grp][2 + t8][tid & 255] = pre1;   // slices 4p+2, 4p+3
        {
            const uint4* src = Q2 + (p + 1) * 1024;
            pre0 = src[tid];                   // slices 4p+4, 4p+5 (p=36 -> 148,149)
            if (p < 36) pre1 = src[512 + tid]; // slices 4p+6, 4p+7
        }
        __syncthreads();
        #pragma unroll
        for (int kk = 0; kk < 4; kk++) {
            int ai = ibase[off];
            const uint4* sb = ring[grp][kk];
            int t = (ai >> 2) & 1;
            uint4 u0 = sb[2 * ai + t];         // o0-7
            uint4 u1 = sb[2 * ai + (t ^ 1)];   // o8-15
            racc[0]  = __dp2a_lo((int)u0.x, 0x00000001, racc[0]);
            racc[1]  = __dp2a_lo((int)u0.x, 0x00000100, racc[1]);
            racc[2]  = __dp2a_lo((int)u0.y, 0x00000001, racc[2]);
            racc[3]  = __dp2a_lo((int)u0.y, 0x00000100, racc[3]);
            racc[4]  = __dp2a_lo((int)u0.z, 0x00000001, racc[4]);
            racc[5]  = __dp2a_lo((int)u0.z, 0x00000100, racc[5]);
            racc[6]  = __dp2a_lo((int)u0.w, 0x00000001, racc[6]);
            racc[7]  = __dp2a_lo((int)u0.w, 0x00000100, racc[7]);
            racc[8]  = __dp2a_lo((int)u1.x, 0x00000001, racc[8]);
            racc[9]  = __dp2a_lo((int)u1.x, 0x00000100, racc[9]);
            racc[10] = __dp2a_lo((int)u1.y, 0x00000001, racc[10]);
            racc[11] = __dp2a_lo((int)u1.y, 0x00000100, racc[11]);
            racc[12] = __dp2a_lo((int)u1.z, 0x00000001, racc[12]);
            racc[13] = __dp2a_lo((int)u1.z, 0x00000100, racc[13]);
            racc[14] = __dp2a_lo((int)u1.w, 0x00000001, racc[14]);
            racc[15] = __dp2a_lo((int)u1.w, 0x00000100, racc[15]);
            off++; jc++;
            if (jc == 5) { jc = 0; off += 7; ic++; if (ic == 5) { ic = 0; off += 84; } }
        }
    }
    // tail: k = 148, 149 (group 1)
    ring[1][t8][tid & 255] = pre0;
    __syncthreads();
    #pragma unroll
    for (int kk = 0; kk < 2; kk++) {
        int ai = ibase[off];
        const uint4* sb = ring[1][kk];
        int t = (ai >> 2) & 1;
        uint4 u0 = sb[2 * ai + t];
        uint4 u1 = sb[2 * ai + (t ^ 1)];
        racc[0]  = __dp2a_lo((int)u0.x, 0x00000001, racc[0]);
        racc[1]  = __dp2a_lo((int)u0.x, 0x00000100, racc[1]);
        racc[2]  = __dp2a_lo((int)u0.y, 0x00000001, racc[2]);
        racc[3]  = __dp2a_lo((int)u0.y, 0x00000100, racc[3]);
        racc[4]  = __dp2a_lo((int)u0.z, 0x00000001, racc[4]);
        racc[5]  = __dp2a_lo((int)u0.z, 0x00000100, racc[5]);
        racc[6]  = __dp2a_lo((int)u0.w, 0x00000001, racc[6]);
        racc[7]  = __dp2a_lo((int)u0.w, 0x00000100, racc[7]);
        racc[8]  = __dp2a_lo((int)u1.x, 0x00000001, racc[8]);
        racc[9]  = __dp2a_lo((int)u1.x, 0x00000100, racc[9]);
        racc[10] = __dp2a_lo((int)u1.y, 0x00000001, racc[10]);
        racc[11] = __dp2a_lo((int)u1.y, 0x00000100, racc[11]);
        racc[12] = __dp2a_lo((int)u1.z, 0x00000001, racc[12]);
        racc[13] = __dp2a_lo((int)u1.z, 0x00000100, racc[13]);
        racc[14] = __dp2a_lo((int)u1.w, 0x00000001, racc[14]);
        racc[15] = __dp2a_lo((int)u1.w, 0x00000100, racc[15]);
        off++; jc++;
        if (jc == 5) { jc = 0; off += 7; ic++; if (ic == 5) { ic = 0; off += 84; } }
    }

    float s = s1 * g_sw[1];
    float v[16];
    #pragma unroll
    for (int o = 0; o < 16; o++)
        v[o] = fmaxf(s * ((float)P[o] + (float)racc[o] * (1.0f / 4096.0f)) + __ldg(b2 + o), 0.0f);

    #pragma unroll
    for (int o = 0; o < 16; o++) {
        v[o] = fmaxf(v[o], __shfl_xor_sync(0xFFFFFFFFu, v[o], 1));
        v[o] = fmaxf(v[o], __shfl_xor_sync(0xFFFFFFFFu, v[o], 8));
    }
    int lane = tid & 31;
    float mymax = 0.0f;
    if (!(lane & 1) && !(lane & 8)) {
        int ppy = y >> 1, ppx = xx >> 1;
        int b = blk * 8 + img;
        #pragma unroll
        for (int o = 0; o < 16; o++) {
            g_h2[(size_t)b * 256 + o * 16 + ppy * 4 + ppx] = v[o];
            mymax = fmaxf(mymax, v[o]);
        }
    }
    float bm = blockReduceMax(mymax, sred);
    if (tid == 0) atomicMax(&g_amax[2], __float_as_uint(bm));
}

// ---------------- fc1 ----------------
__global__ void __launch_bounds__(128) k_fc1(const float* fcb) {
    __shared__ u8 q[256];
    __shared__ float sred[32];
    int b = blockIdx.x, tid = threadIdx.x;
    float s2 = act_scale(2);
    for (int i = tid; i < 256; i += 128) q[i] = quant1(g_h2[(size_t)b * 256 + i], s2);
    __syncthreads();
    float acc = 0.0f;
    if (tid < 120) {
        #pragma unroll 8
        for (int k = 0; k < 256; k++) {
            int ai = (int)q[k] - 128;
            acc += __ldg(&g_M3[(size_t)(k * 128 + ai) * 120 + tid]);
        }
    }
    float s = s2 * g_sw[2];
    float val = 0.0f;
    if (tid < 120) {
        val = fmaxf(s * acc + __ldg(fcb + tid), 0.0f);
        g_h3[(size_t)b * 120 + tid] = val;
    }
    float bm = blockReduceMax(val, sred);
    if (tid == 0) atomicMax(&g_amax[3], __float_as_uint(bm));
}

// ---------------- fc2 ----------------
__global__ void __launch_bounds__(96) k_fc2(const float* fcb) {
    __shared__ u8 q[120];
    __shared__ float sred[32];
    int b = blockIdx.x, tid = threadIdx.x;
    float s3 = act_scale(3);
    for (int i = tid; i < 120; i += 96) q[i] = quant1(g_h3[(size_t)b * 120 + i], s3);
    __syncthreads();
    float acc = 0.0f;
    if (tid < 84) {
        #pragma unroll 8
        for (int k = 0; k < 120; k++) {
            int ai = (int)q[k] - 128;
            acc += __ldg(&g_M4[(size_t)(k * 128 + ai) * 84 + tid]);
        }
    }
    float s = s3 * g_sw[3];
    float val = 0.0f;
    if (tid < 84) {
        val = fmaxf(s * acc + __ldg(fcb + tid), 0.0f);
        g_h4[(size_t)b * 84 + tid] = val;
    }
    float bm = blockReduceMax(val, sred);
    if (tid == 0) atomicMax(&g_amax[4], __float_as_uint(bm));
}

// ---------------- fc3 ----------------
__global__ void __launch_bounds__(96) k_fc3(const float* fcb, float* out) {
    __shared__ u8 q[84];
    int b = blockIdx.x, tid = threadIdx.x;
    float s4 = act_scale(4);
    if (tid < 84) q[tid] = quant1(g_h4[(size_t)b * 84 + tid], s4);
    __syncthreads();
    if (tid < 10) {
        float acc = 0.0f;
        #pragma unroll 4
        for (int k = 0; k < 84; k++) {
            int ai = (int)q[k] - 128;
            acc += __ldg(&g_M5[(k * 128 + ai) * 10 + tid]);
        }
        out[b * 10 + tid] = s4 * g_sw[4] * acc + __ldg(fcb + tid);
    }
}

// ---------------- launch ----------------
extern "C" void kernel_launch(void* const* d_in, const int* in_sizes, int n_in,
                              void* d_out, int out_size) {
    const float* x   = (const float*)d_in[0];
    const float* lut = (const float*)d_in[1];
    const float* w1  = (const float*)d_in[2];
    const float* b1  = (const float*)d_in[3];
    const float* w2  = (const float*)d_in[4];
    const float* b2  = (const float*)d_in[5];
    const float* w3  = (const float*)d_in[6];
    const float* b3  = (const float*)d_in[7];
    const float* w4  = (const float*)d_in[8];
    const float* b4  = (const float*)d_in[9];
    const float* w5  = (const float*)d_in[10];
    const float* b5  = (const float*)d_in[11];
    float* out = (float*)d_out;

    cudaFuncSetAttribute(k_conv1, cudaFuncAttributeMaxDynamicSharedMemorySize, C1_SMEM);

    int nx = BATCH * 784;
    k_setup<<<5 + 2048, 256>>>(w1, w2, w3, w4, w5, x, nx);              // 1
    k_buildS12<<<(S1_TOT + S2_TOT + 255) / 256, 256>>>(lut);            // 2
    k_conv1<<<296, 576, C1_SMEM>>>(x, b1);                              // 3
    k_conv2<<<BATCH / 8, 512>>>(b2);                                    // 4  <- profiled
    k_buildM345<<<20832, 256>>>(lut);                                   // 5
    k_fc1<<<BATCH, 128>>>(b3);                                          // 6
    k_fc2<<<BATCH, 96>>>(b4);                                           // 7
    k_fc3<<<BATCH, 96>>>(b5, out);                                      // 8
}